// round 9
// baseline (speedup 1.0000x reference)
#include <cuda_runtime.h>
#include <cstdint>

// Modulated deformable conv 3x3, in_ch=out_ch=1, stride=1, pad=1, dil=1.
// H=W=512 hardcoded. R9: R8 (2 rows/thread, vertical gathers, warp-
// cooperative cp.async staging) with register-lean pipeline addressing
// (single base + constant per-stage offsets), NS=4, 6 CTAs/SM target.

#define Hc 512
#define Wc 512
#define HWc (Hc * Wc)
#define NS 4                      // pipeline stages
#define SLAB_FLOATS 192           // dy[64] dx[64] m[64] per warp per stage
#define STAGE_BYTES (8 * SLAB_FLOATS * 4)   // stride between stages (all warps)

__device__ __forceinline__ uint32_t smem_u32(const void* p) {
    uint32_t a;
    asm("{ .reg .u64 t; cvta.to.shared.u64 t, %1; cvt.u32.u64 %0, t; }"
        : "=r"(a) : "l"(p));
    return a;
}

#define CP_ASYNC_16(dst, src) \
    asm volatile("cp.async.cg.shared.global [%0], [%1], 16;" \
                 :: "r"(dst), "l"(src) : "memory")
#define CP_COMMIT() asm volatile("cp.async.commit_group;" ::: "memory")
#define CP_WAIT(n)  asm volatile("cp.async.wait_group %0;" :: "n"(n) : "memory")

__device__ __forceinline__ float bilin_sample(const float* __restrict__ img,
                                              float y, float x) {
    float y0f = floorf(y);
    float x0f = floorf(x);
    float wy = y - y0f;
    float wx = x - x0f;
    int y0 = (int)y0f;
    int x0 = (int)x0f;
    int base = (y0 << 9) + x0;   // W = 512
    bool vy0 = (unsigned)y0 < (unsigned)Hc;
    bool vy1 = (unsigned)(y0 + 1) < (unsigned)Hc;
    bool vx0 = (unsigned)x0 < (unsigned)Wc;
    bool vx1 = (unsigned)(x0 + 1) < (unsigned)Wc;
    float v00 = (vy0 && vx0) ? __ldg(img + base)          : 0.0f;
    float v01 = (vy0 && vx1) ? __ldg(img + base + 1)      : 0.0f;
    float v10 = (vy1 && vx0) ? __ldg(img + base + Wc)     : 0.0f;
    float v11 = (vy1 && vx1) ? __ldg(img + base + Wc + 1) : 0.0f;
    float top = fmaf(wx, v01 - v00, v00);
    float bot = fmaf(wx, v11 - v10, v10);
    return fmaf(wy, bot - top, top);
}

__global__ __launch_bounds__(256, 6)
void dcn_kernel(const float* __restrict__ depth,
                const float* __restrict__ mask,
                const float* __restrict__ off,
                const float* __restrict__ w9,
                const float* __restrict__ bias,
                float* __restrict__ out,
                int B)
{
    // [stage][warp][192 floats]: dy(2 rows x 32) | dx | m
    __shared__ __align__(16) float slab[NS][8][SLAB_FLOATS];

    int tid  = threadIdx.x;
    int lane = tid & 31;
    int wrp  = tid >> 5;
    int bid  = blockIdx.x;
    int b    = bid >> 9;          // 512 blocks per image
    int rem  = bid & 511;
    int ys   = rem >> 1;          // 256 y-strips of 2 rows
    int xs   = rem & 1;           // 2 x-strips of 256 px
    int y0   = ys << 1;
    int xw   = (xs << 8) + (wrp << 5);   // warp x origin
    int x    = xw + lane;

    const float* img   = depth + (size_t)b * HWc;
    const float* obase = off   + (size_t)b * 18 * HWc + (y0 << 9) + xw;
    const float* mbase = mask  + (size_t)b * 9  * HWc + (y0 << 9) + xw;

    // Cooperative copy mapping:
    //  instrA (32 lanes): arr = lane>>4 selects dy/dx plane; cc = lane&15 is
    //    the 16B chunk (row cc>>3, x-segment cc&7).
    //  instrB (lanes 0..15): mask plane, chunk = lane.
    int arr  = lane >> 4;
    int cc   = lane & 15;
    int coff = ((cc >> 3) << 9) + ((cc & 7) << 2);       // floats
    int moff = ((lane >> 3) << 9) + ((lane & 7) << 2);   // floats (lane<16)

    // Single base address; per-stage offsets are unroll-time constants.
    uint32_t warp_base = smem_u32(&slab[0][wrp][0]);
    uint32_t adst0 = warp_base + (uint32_t)lane * 16;    // dy+dx region
    uint32_t bdst0 = warp_base + 512 + (uint32_t)lane * 16;  // m region

    // Prologue: stage taps 0..NS-1, one commit group per tap
    #pragma unroll
    for (int t = 0; t < NS; t++) {
        CP_ASYNC_16(adst0 + t * STAGE_BYTES, obase + (size_t)(2 * t + arr) * HWc + coff);
        if (lane < 16)
            CP_ASYNC_16(bdst0 + t * STAGE_BYTES, mbase + (size_t)t * HWc + moff);
        CP_COMMIT();
    }

    float wreg[9];
    #pragma unroll
    for (int t = 0; t < 9; t++) wreg[t] = __ldg(w9 + t);

    float acc0 = 0.0f, acc1 = 0.0f;
    float xf = (float)x;

    #pragma unroll
    for (int t = 0; t < 9; t++) {
        const int s = t % NS;

        CP_WAIT(NS - 1);        // tap t's group complete (this lane)
        __syncwarp();           // whole warp's chunks visible

        const float* f = &slab[s][wrp][0];
        float dy0 = f[lane],       dy1 = f[32 + lane];
        float dx0 = f[64 + lane],  dx1 = f[96 + lane];
        float m0  = f[128 + lane], m1  = f[160 + lane];

        __syncwarp();           // all lanes done reading stage s

        int tn = t + NS;
        if (tn < 9) {
            CP_ASYNC_16(adst0 + s * STAGE_BYTES, obase + (size_t)(2 * tn + arr) * HWc + coff);
            if (lane < 16)
                CP_ASYNC_16(bdst0 + s * STAGE_BYTES, mbase + (size_t)tn * HWc + moff);
        }
        CP_COMMIT();            // one group per iteration (empty ok)

        float wt = wreg[t];
        float ybase = (float)(y0 - 1 + t / 3);
        float xtap  = xf + (float)(t % 3 - 1);

        float sv;
        sv = bilin_sample(img, ybase + 0.0f + dy0, xtap + dx0);
        acc0 = fmaf(sv, m0 * wt, acc0);
        sv = bilin_sample(img, ybase + 1.0f + dy1, xtap + dx1);
        acc1 = fmaf(sv, m1 * wt, acc1);
    }

    float bv = __ldg(bias);
    float* optr = out + (size_t)b * HWc + (y0 << 9) + x;
    optr[0]  = acc0 + bv;
    optr[Wc] = acc1 + bv;
}

extern "C" void kernel_launch(void* const* d_in, const int* in_sizes, int n_in,
                              void* d_out, int out_size)
{
    const float* depth = (const float*)d_in[0];
    const float* mask  = (const float*)d_in[1];
    const float* off   = (const float*)d_in[2];
    const float* w9    = (const float*)d_in[3];
    const float* bias  = (const float*)d_in[4];
    float* out = (float*)d_out;

    int B = in_sizes[0] / HWc;
    int blocks = B * 512;       // 512 blocks per 512x512 image
    dcn_kernel<<<blocks, 256>>>(depth, mask, off, w9, bias, out, B);
}

// round 10
// speedup vs baseline: 1.0144x; 1.0144x over previous
#include <cuda_runtime.h>
#include <cstdint>

// Modulated deformable conv 3x3, in_ch=out_ch=1, stride=1, pad=1, dil=1.
// H=W=512 hardcoded. R10: R9 with aggressive register diet for 8 CTAs/SM
// (64 warps): weights reloaded per tap (no 9-reg array), NS=3 ring,
// launch_bounds(256,8). Streaming stays in smem via warp-cooperative
// cp.async; gathers vertical (2 rows/thread).

#define Hc 512
#define Wc 512
#define HWc (Hc * Wc)
#define NS 3                      // pipeline stages
#define SLAB_FLOATS 192           // dy[64] dx[64] m[64] per warp per stage
#define STAGE_BYTES (8 * SLAB_FLOATS * 4)   // stride between stages

__device__ __forceinline__ uint32_t smem_u32(const void* p) {
    uint32_t a;
    asm("{ .reg .u64 t; cvta.to.shared.u64 t, %1; cvt.u32.u64 %0, t; }"
        : "=r"(a) : "l"(p));
    return a;
}

#define CP_ASYNC_16(dst, src) \
    asm volatile("cp.async.cg.shared.global [%0], [%1], 16;" \
                 :: "r"(dst), "l"(src) : "memory")
#define CP_COMMIT() asm volatile("cp.async.commit_group;" ::: "memory")
#define CP_WAIT(n)  asm volatile("cp.async.wait_group %0;" :: "n"(n) : "memory")

__device__ __forceinline__ float bilin_sample(const float* __restrict__ img,
                                              float y, float x) {
    float y0f = floorf(y);
    float x0f = floorf(x);
    float wy = y - y0f;
    float wx = x - x0f;
    int y0 = (int)y0f;
    int x0 = (int)x0f;
    int base = (y0 << 9) + x0;   // W = 512
    bool vy0 = (unsigned)y0 < (unsigned)Hc;
    bool vy1 = (unsigned)(y0 + 1) < (unsigned)Hc;
    bool vx0 = (unsigned)x0 < (unsigned)Wc;
    bool vx1 = (unsigned)(x0 + 1) < (unsigned)Wc;
    float v00 = (vy0 && vx0) ? __ldg(img + base)          : 0.0f;
    float v01 = (vy0 && vx1) ? __ldg(img + base + 1)      : 0.0f;
    float v10 = (vy1 && vx0) ? __ldg(img + base + Wc)     : 0.0f;
    float v11 = (vy1 && vx1) ? __ldg(img + base + Wc + 1) : 0.0f;
    float top = fmaf(wx, v01 - v00, v00);
    float bot = fmaf(wx, v11 - v10, v10);
    return fmaf(wy, bot - top, top);
}

__global__ __launch_bounds__(256, 8)
void dcn_kernel(const float* __restrict__ depth,
                const float* __restrict__ mask,
                const float* __restrict__ off,
                const float* __restrict__ w9,
                const float* __restrict__ bias,
                float* __restrict__ out,
                int B)
{
    // [stage][warp][192 floats]: dy(2 rows x 32) | dx | m
    __shared__ __align__(16) float slab[NS][8][SLAB_FLOATS];

    int tid  = threadIdx.x;
    int lane = tid & 31;
    int wrp  = tid >> 5;
    int bid  = blockIdx.x;
    int b    = bid >> 9;          // 512 blocks per image
    int rem  = bid & 511;
    int ys   = rem >> 1;          // 256 y-strips of 2 rows
    int xs   = rem & 1;           // 2 x-strips of 256 px
    int y0   = ys << 1;
    int xw   = (xs << 8) + (wrp << 5);   // warp x origin
    int x    = xw + lane;

    const float* img   = depth + (size_t)b * HWc;
    const float* obase = off   + (size_t)b * 18 * HWc + (y0 << 9) + xw;
    const float* mbase = mask  + (size_t)b * 9  * HWc + (y0 << 9) + xw;

    // Cooperative copy mapping:
    //  instrA (32 lanes): arr = lane>>4 selects dy/dx plane; cc = lane&15 is
    //    the 16B chunk (row cc>>3, x-segment cc&7).
    //  instrB (lanes 0..15): mask plane, chunk = lane.
    int arr  = lane >> 4;
    int cc   = lane & 15;
    int coff = ((cc >> 3) << 9) + ((cc & 7) << 2);       // floats
    int moff = ((lane >> 3) << 9) + ((lane & 7) << 2);   // floats (lane<16)

    uint32_t warp_base = smem_u32(&slab[0][wrp][0]);
    uint32_t adst0 = warp_base + (uint32_t)lane * 16;        // dy+dx region
    uint32_t bdst0 = warp_base + 512 + (uint32_t)lane * 16;  // m region

    // Prologue: stage taps 0..NS-1, one commit group per tap
    #pragma unroll
    for (int t = 0; t < NS; t++) {
        CP_ASYNC_16(adst0 + t * STAGE_BYTES, obase + (size_t)(2 * t + arr) * HWc + coff);
        if (lane < 16)
            CP_ASYNC_16(bdst0 + t * STAGE_BYTES, mbase + (size_t)t * HWc + moff);
        CP_COMMIT();
    }

    float acc0 = 0.0f, acc1 = 0.0f;
    float xf = (float)x;

    #pragma unroll
    for (int t = 0; t < 9; t++) {
        const int s = t % NS;

        CP_WAIT(NS - 1);        // tap t's group complete (this lane)
        __syncwarp();           // whole warp's chunks visible

        const float* f = &slab[s][wrp][0];
        float dy0 = f[lane],       dy1 = f[32 + lane];
        float dx0 = f[64 + lane],  dx1 = f[96 + lane];
        float m0  = f[128 + lane], m1  = f[160 + lane];

        // NOTE: no second __syncwarp needed — warp executes in lockstep, so
        // all lanes' LDS reads above retire before any lane's cp.async below
        // can overwrite the slot (async writes land strictly later).

        int tn = t + NS;
        if (tn < 9) {
            CP_ASYNC_16(adst0 + s * STAGE_BYTES, obase + (size_t)(2 * tn + arr) * HWc + coff);
            if (lane < 16)
                CP_ASYNC_16(bdst0 + s * STAGE_BYTES, mbase + (size_t)tn * HWc + moff);
        }
        CP_COMMIT();            // one group per iteration (empty ok)

        float wt = __ldg(w9 + t);           // L1-hit, 1 live reg (no array)
        float ybase = (float)(y0 - 1 + t / 3);
        float xtap  = xf + (float)(t % 3 - 1);

        float sv;
        sv = bilin_sample(img, ybase + 0.0f + dy0, xtap + dx0);
        acc0 = fmaf(sv, m0 * wt, acc0);
        sv = bilin_sample(img, ybase + 1.0f + dy1, xtap + dx1);
        acc1 = fmaf(sv, m1 * wt, acc1);
    }

    float bv = __ldg(bias);
    float* optr = out + (size_t)b * HWc + (y0 << 9) + x;
    optr[0]  = acc0 + bv;
    optr[Wc] = acc1 + bv;
}

extern "C" void kernel_launch(void* const* d_in, const int* in_sizes, int n_in,
                              void* d_out, int out_size)
{
    const float* depth = (const float*)d_in[0];
    const float* mask  = (const float*)d_in[1];
    const float* off   = (const float*)d_in[2];
    const float* w9    = (const float*)d_in[3];
    const float* bias  = (const float*)d_in[4];
    float* out = (float*)d_out;

    int B = in_sizes[0] / HWc;
    int blocks = B * 512;       // 512 blocks per 512x512 image
    dcn_kernel<<<blocks, 256>>>(depth, mask, off, w9, bias, out, B);
}